// round 12
// baseline (speedup 1.0000x reference)
#include <cuda_runtime.h>
#include <cuda_bf16.h>
#include <cstddef>

#define LSEQ 768
#define DDIM 128
#define BATCH 16

__device__ __forceinline__ float4 ld4(const float* p) { return *(const float4*)p; }

static constexpr float INV_T = 0.08838834764831843f;  // 1/sqrt(128)

// ---- packed f32x2 helpers (sm_103a FFMA2 path, PTX-only) -------------------
__device__ __forceinline__ unsigned long long pk2(float lo, float hi) {
    unsigned long long r;
    asm("mov.b64 %0, {%1, %2};" : "=l"(r) : "f"(lo), "f"(hi));
    return r;
}
__device__ __forceinline__ void fma2(unsigned long long& d,
                                     unsigned long long a, unsigned long long b) {
    asm("fma.rn.f32x2 %0, %1, %2, %0;" : "+l"(d) : "l"(a), "l"(b));
}
__device__ __forceinline__ float2 upk2(unsigned long long v) {
    float2 f;
    asm("mov.b64 {%0, %1}, %2;" : "=f"(f.x), "=f"(f.y) : "l"(v));
    return f;
}

// ---------------------------------------------------------------------------
// Kernel 1: S = (Q K^T + local + D*fc_b) * INV_T  -> attn scratch.
// Tile 96x96, micro-tile 6x6 per thread = 2x2 CLIP(3) cells. FFMA2 inner loop:
// k-direction float2 smem reads ARE the packed operands; q side broadcast-packed.
// ---------------------------------------------------------------------------
__global__ __launch_bounds__(256) void scores_kernel(
    const float* __restrict__ q, const float* __restrict__ k,
    const float* __restrict__ fc_w, const float* __restrict__ fc_b,
    float* __restrict__ attn)
{
    __shared__ float Qs[32][100];   // [d within chunk][row]
    __shared__ float Ks[32][100];

    const int b  = blockIdx.z;
    const int qt = blockIdx.y;
    const int kt = blockIdx.x;
    const int t  = threadIdx.x;
    const int ty = t >> 4;          // 0..15 -> q rows 6*ty..6*ty+5
    const int tx = t & 15;          // 0..15 -> k cols 6*tx..6*tx+5

    unsigned long long acc2[6][3] = {};   // 6 q-rows x 3 packed k-pairs

    const float* qbase = q + ((size_t)b * LSEQ + qt * 96) * DDIM;
    const float* kbase = k + ((size_t)b * LSEQ + kt * 96) * DDIM;

    for (int dc = 0; dc < 4; ++dc) {               // four 32-wide D chunks
        #pragma unroll
        for (int i = 0; i < 3; ++i) {              // 96 rows * 8 float4 = 768 per side
            int idx = t + i * 256;
            int row = idx >> 3;                    // 0..95
            int c4  = idx & 7;                     // 0..7
            float4 qv = ld4(qbase + row * DDIM + dc * 32 + c4 * 4);
            float4 kv = ld4(kbase + row * DDIM + dc * 32 + c4 * 4);
            Qs[c4 * 4 + 0][row] = qv.x;
            Qs[c4 * 4 + 1][row] = qv.y;
            Qs[c4 * 4 + 2][row] = qv.z;
            Qs[c4 * 4 + 3][row] = qv.w;
            Ks[c4 * 4 + 0][row] = kv.x;
            Ks[c4 * 4 + 1][row] = kv.y;
            Ks[c4 * 4 + 2][row] = kv.z;
            Ks[c4 * 4 + 3][row] = kv.w;
        }
        __syncthreads();

        #pragma unroll
        for (int d = 0; d < 32; ++d) {
            float2 q0 = *(const float2*)&Qs[d][6 * ty + 0];
            float2 q1 = *(const float2*)&Qs[d][6 * ty + 2];
            float2 q2 = *(const float2*)&Qs[d][6 * ty + 4];
            unsigned long long kv0 = *(const unsigned long long*)&Ks[d][6 * tx + 0];
            unsigned long long kv1 = *(const unsigned long long*)&Ks[d][6 * tx + 2];
            unsigned long long kv2v = *(const unsigned long long*)&Ks[d][6 * tx + 4];
            const float qv[6] = {q0.x, q0.y, q1.x, q1.y, q2.x, q2.y};
            #pragma unroll
            for (int a = 0; a < 6; ++a) {
                unsigned long long qa = pk2(qv[a], qv[a]);
                fma2(acc2[a][0], qa, kv0);
                fma2(acc2[a][1], qa, kv1);
                fma2(acc2[a][2], qa, kv2v);
            }
        }
        __syncthreads();
    }

    // unpack accumulators
    float acc[6][6];
    #pragma unroll
    for (int a = 0; a < 6; ++a)
        #pragma unroll
        for (int p = 0; p < 3; ++p) {
            float2 f = upk2(acc2[a][p]);
            acc[a][2 * p + 0] = f.x;
            acc[a][2 * p + 1] = f.y;
        }

    // local term per 2x2 CLIP cells (thread-private)
    float w[9];
    #pragma unroll
    for (int i = 0; i < 9; ++i) w[i] = fc_w[i];
    const float base = 128.0f * fc_b[0];
    float loc[2][2];
    #pragma unroll
    for (int A = 0; A < 2; ++A)
        #pragma unroll
        for (int C = 0; C < 2; ++C) {
            float s = base;
            #pragma unroll
            for (int a = 0; a < 3; ++a)
                #pragma unroll
                for (int c = 0; c < 3; ++c)
                    s += w[a * 3 + c] * acc[3 * A + a][3 * C + c];
            loc[A][C] = s;
        }

    float* outp = attn + ((size_t)b * LSEQ + qt * 96 + 6 * ty) * LSEQ + kt * 96 + 6 * tx;
    #pragma unroll
    for (int r = 0; r < 6; ++r) {
        const int A = r / 3;
        #pragma unroll
        for (int c2 = 0; c2 < 3; ++c2) {
            float2 vv;
            vv.x = (acc[r][2 * c2 + 0] + loc[A][(2 * c2 + 0) / 3]) * INV_T;
            vv.y = (acc[r][2 * c2 + 1] + loc[A][(2 * c2 + 1) / 3]) * INV_T;
            *(float2*)(outp + (size_t)r * LSEQ + 2 * c2) = vv;
        }
    }
}

// ---------------------------------------------------------------------------
// Kernel 2: in-place row softmax over len_k = 768. One block per (b, q) row.
// ---------------------------------------------------------------------------
__global__ __launch_bounds__(256) void softmax_kernel(float* __restrict__ attn)
{
    const int row = blockIdx.x;
    float* p = attn + (size_t)row * LSEQ;
    const int t = threadIdx.x;

    __shared__ float red[8];

    float v0 = p[t], v1 = p[t + 256], v2 = p[t + 512];
    float m = fmaxf(fmaxf(v0, v1), v2);
    #pragma unroll
    for (int off = 16; off; off >>= 1)
        m = fmaxf(m, __shfl_xor_sync(0xffffffffu, m, off));
    if ((t & 31) == 0) red[t >> 5] = m;
    __syncthreads();
    m = fmaxf(fmaxf(fmaxf(red[0], red[1]), fmaxf(red[2], red[3])),
              fmaxf(fmaxf(red[4], red[5]), fmaxf(red[6], red[7])));
    __syncthreads();

    v0 = __expf(v0 - m); v1 = __expf(v1 - m); v2 = __expf(v2 - m);
    float s = v0 + v1 + v2;
    #pragma unroll
    for (int off = 16; off; off >>= 1)
        s += __shfl_xor_sync(0xffffffffu, s, off);
    if ((t & 31) == 0) red[t >> 5] = s;
    __syncthreads();
    s = (red[0] + red[1]) + (red[2] + red[3]) + (red[4] + red[5]) + (red[6] + red[7]);
    float inv = __frcp_rn(s);

    p[t]       = v0 * inv;
    p[t + 256] = v1 * inv;
    p[t + 512] = v2 * inv;
}

// ---------------------------------------------------------------------------
// Kernel 3: output = attn @ V. Tile 96x128, thread = 6x8, FFMA2 inner loop.
// ---------------------------------------------------------------------------
__global__ __launch_bounds__(256) void out_kernel(
    const float* __restrict__ attn, const float* __restrict__ v,
    float* __restrict__ out)
{
    __shared__ float As[32][100];   // [kk][q-row]
    __shared__ float Vs[32][132];   // [kk][d-col]

    const int b  = blockIdx.y;
    const int qt = blockIdx.x;
    const int t  = threadIdx.x;
    const int ty = t >> 4;          // 0..15 -> q rows 6*ty..6*ty+5
    const int tx = t & 15;          // 0..15 -> d cols 8*tx..8*tx+7

    unsigned long long acc2[6][4] = {};   // 6 q-rows x 4 packed d-pairs

    const float* arow = attn + ((size_t)b * LSEQ + qt * 96) * LSEQ;
    const float* vb   = v + (size_t)b * LSEQ * DDIM;

    for (int k0 = 0; k0 < LSEQ; k0 += 32) {
        // attn tile 96 rows x 32 cols -> transposed: 768 float4 / 256 thr
        #pragma unroll
        for (int i = 0; i < 3; ++i) {
            int idx = t + i * 256;
            int row = idx >> 3;                    // 0..95
            int c4  = idx & 7;                     // 0..7
            float4 av = ld4(arow + (size_t)row * LSEQ + k0 + c4 * 4);
            As[c4 * 4 + 0][row] = av.x;
            As[c4 * 4 + 1][row] = av.y;
            As[c4 * 4 + 2][row] = av.z;
            As[c4 * 4 + 3][row] = av.w;
        }
        // V tile 32 rows x 128 cols = 1024 float4 / 256 thr = 4 each
        #pragma unroll
        for (int i = 0; i < 4; ++i) {
            int idx = t + i * 256;
            int row = idx >> 5;                    // 0..31
            int c4  = idx & 31;
            *(float4*)&Vs[row][c4 * 4] = ld4(vb + (size_t)(k0 + row) * DDIM + c4 * 4);
        }
        __syncthreads();

        #pragma unroll
        for (int kk = 0; kk < 32; ++kk) {
            float2 a0 = *(const float2*)&As[kk][6 * ty + 0];
            float2 a1 = *(const float2*)&As[kk][6 * ty + 2];
            float2 a2 = *(const float2*)&As[kk][6 * ty + 4];
            const unsigned long long* vp =
                (const unsigned long long*)&Vs[kk][tx * 8];
            unsigned long long w0 = vp[0], w1 = vp[1], w2 = vp[2], w3 = vp[3];
            const float av[6] = {a0.x, a0.y, a1.x, a1.y, a2.x, a2.y};
            #pragma unroll
            for (int r = 0; r < 6; ++r) {
                unsigned long long ar = pk2(av[r], av[r]);
                fma2(acc2[r][0], ar, w0);
                fma2(acc2[r][1], ar, w1);
                fma2(acc2[r][2], ar, w2);
                fma2(acc2[r][3], ar, w3);
            }
        }
        __syncthreads();
    }

    float* op = out + ((size_t)b * LSEQ + qt * 96 + 6 * ty) * DDIM + tx * 8;
    #pragma unroll
    for (int r = 0; r < 6; ++r) {
        float2 f0 = upk2(acc2[r][0]);
        float2 f1 = upk2(acc2[r][1]);
        float2 f2 = upk2(acc2[r][2]);
        float2 f3 = upk2(acc2[r][3]);
        float4 s0 = make_float4(f0.x, f0.y, f1.x, f1.y);
        float4 s1 = make_float4(f2.x, f2.y, f3.x, f3.y);
        *(float4*)(op + (size_t)r * DDIM)     = s0;
        *(float4*)(op + (size_t)r * DDIM + 4) = s1;
    }
}

// ---------------------------------------------------------------------------
extern "C" void kernel_launch(void* const* d_in, const int* in_sizes, int n_in,
                              void* d_out, int out_size)
{
    const float* q    = (const float*)d_in[0];
    const float* k    = (const float*)d_in[1];
    const float* v    = (const float*)d_in[2];
    const float* fc_w = (const float*)d_in[3];
    const float* fc_b = (const float*)d_in[4];

    float* out  = (float*)d_out;                                  // (B, L, D)
    float* attn = out + (size_t)BATCH * LSEQ * DDIM;              // (B, L, L)

    dim3 g1(LSEQ / 96, LSEQ / 96, BATCH);
    scores_kernel<<<g1, 256>>>(q, k, fc_w, fc_b, attn);

    softmax_kernel<<<BATCH * LSEQ, 256>>>(attn);

    dim3 g3(LSEQ / 96, BATCH);
    out_kernel<<<g3, 256>>>(attn, v, out);
}

// round 16
// speedup vs baseline: 1.0518x; 1.0518x over previous
#include <cuda_runtime.h>
#include <cuda_bf16.h>
#include <cstddef>
#include <cstdint>

#define LSEQ 768
#define DDIM 128
#define BATCH 16
#define NBLK 256   // LSEQ / CLIP

static constexpr float INV_T = 0.08838834764831843f;  // 1/sqrt(128)

__device__ __forceinline__ float4 ld4(const float* p) { return *(const float4*)p; }

// 4MB scratch for local block sums (static __device__ allowed)
__device__ float locbuf[BATCH * NBLK * NBLK];

// ---- bf16 hi/lo split of a float4 -> packed bf16x2 pairs -------------------
__device__ __forceinline__ void cvt4(float4 v, uint2& hi, uint2& lo) {
    __nv_bfloat16 h0 = __float2bfloat16(v.x), h1 = __float2bfloat16(v.y);
    __nv_bfloat16 h2 = __float2bfloat16(v.z), h3 = __float2bfloat16(v.w);
    __nv_bfloat16 l0 = __float2bfloat16(v.x - __bfloat162float(h0));
    __nv_bfloat16 l1 = __float2bfloat16(v.y - __bfloat162float(h1));
    __nv_bfloat16 l2 = __float2bfloat16(v.z - __bfloat162float(h2));
    __nv_bfloat16 l3 = __float2bfloat16(v.w - __bfloat162float(h3));
    hi.x = ((uint32_t)__bfloat16_as_ushort(h1) << 16) | __bfloat16_as_ushort(h0);
    hi.y = ((uint32_t)__bfloat16_as_ushort(h3) << 16) | __bfloat16_as_ushort(h2);
    lo.x = ((uint32_t)__bfloat16_as_ushort(l1) << 16) | __bfloat16_as_ushort(l0);
    lo.y = ((uint32_t)__bfloat16_as_ushort(l3) << 16) | __bfloat16_as_ushort(l2);
}

// warp mma: D += A(16x16 bf16, row) * B(16x8 bf16, col)
__device__ __forceinline__ void mma_bf16(float* d, const uint32_t* a,
                                         uint32_t b0, uint32_t b1) {
    asm volatile(
        "mma.sync.aligned.m16n8k16.row.col.f32.bf16.bf16.f32 "
        "{%0,%1,%2,%3}, {%4,%5,%6,%7}, {%8,%9}, {%0,%1,%2,%3};"
        : "+f"(d[0]), "+f"(d[1]), "+f"(d[2]), "+f"(d[3])
        : "r"(a[0]), "r"(a[1]), "r"(a[2]), "r"(a[3]), "r"(b0), "r"(b1));
}

// smem tile geometry: 128 rows x 128 bf16, row stride 272 B (68 words = 4 mod 32
// -> fragment loads conflict-free). 4 tiles (Qh, Ql, Kh, Kl).
#define RS 272
static constexpr int T_BYTES = 128 * RS;        // 34816
static constexpr int SMEM_DYN = 4 * T_BYTES;    // 139264

__device__ __forceinline__ uint32_t lds32(const char* p) {
    return *(const uint32_t*)p;
}

// ---------------------------------------------------------------------------
// Kernel 1 (tensor, HMMA): S_raw = Q K^T via bf16 hi/lo split (hh + hl + lh).
// CTA tile 128x128x128; 8 warps, warp tile 32x64 (2 x 8 m16n8k16 frags).
// ---------------------------------------------------------------------------
__global__ __launch_bounds__(256) void scores_tc_kernel(
    const float* __restrict__ q, const float* __restrict__ k,
    float* __restrict__ sraw)
{
    extern __shared__ char sm[];
    char* QH = sm;
    char* QL = sm + T_BYTES;
    char* KH = sm + 2 * T_BYTES;
    char* KL = sm + 3 * T_BYTES;

    const int t = threadIdx.x;
    const int warp = t >> 5, lane = t & 31;
    const int b = blockIdx.z, qt = blockIdx.y, kt = blockIdx.x;

    // load + hi/lo split: thread = (row, 64-col half)
    {
        const int row = t >> 1, h = t & 1;
        const float* qsrc = q + ((size_t)b * LSEQ + qt * 128 + row) * DDIM + h * 64;
        const float* ksrc = k + ((size_t)b * LSEQ + kt * 128 + row) * DDIM + h * 64;
        #pragma unroll
        for (int j = 0; j < 16; ++j) {
            const int off = row * RS + (h * 64 + j * 4) * 2;
            uint2 hi, lo;
            cvt4(ld4(qsrc + j * 4), hi, lo);
            *(uint2*)(QH + off) = hi;
            *(uint2*)(QL + off) = lo;
            cvt4(ld4(ksrc + j * 4), hi, lo);
            *(uint2*)(KH + off) = hi;
            *(uint2*)(KL + off) = lo;
        }
    }
    __syncthreads();

    const int mbase = (warp >> 1) * 32;     // warp rows
    const int nbase = (warp & 1) * 64;      // warp cols
    const int gid = lane >> 2, tid4 = lane & 3;

    float acc[2][8][4];
    #pragma unroll
    for (int m = 0; m < 2; ++m)
        #pragma unroll
        for (int n = 0; n < 8; ++n)
            #pragma unroll
            for (int x = 0; x < 4; ++x) acc[m][n][x] = 0.0f;

    #pragma unroll
    for (int k0 = 0; k0 < 128; k0 += 16) {
        uint32_t ah[2][4], al[2][4];
        #pragma unroll
        for (int m = 0; m < 2; ++m) {
            const int oA = (mbase + m * 16 + gid) * RS + (k0 + 2 * tid4) * 2;
            ah[m][0] = lds32(QH + oA);
            ah[m][1] = lds32(QH + oA + 8 * RS);
            ah[m][2] = lds32(QH + oA + 16);
            ah[m][3] = lds32(QH + oA + 8 * RS + 16);
            al[m][0] = lds32(QL + oA);
            al[m][1] = lds32(QL + oA + 8 * RS);
            al[m][2] = lds32(QL + oA + 16);
            al[m][3] = lds32(QL + oA + 8 * RS + 16);
        }
        #pragma unroll
        for (int n = 0; n < 8; ++n) {
            const int oB = (nbase + n * 8 + gid) * RS + (k0 + 2 * tid4) * 2;
            const uint32_t bh0 = lds32(KH + oB), bh1 = lds32(KH + oB + 16);
            const uint32_t bl0 = lds32(KL + oB), bl1 = lds32(KL + oB + 16);
            #pragma unroll
            for (int m = 0; m < 2; ++m) {
                mma_bf16(acc[m][n], ah[m], bh0, bh1);   // hh
                mma_bf16(acc[m][n], ah[m], bl0, bl1);   // h*l
                mma_bf16(acc[m][n], al[m], bh0, bh1);   // l*h
            }
        }
    }

    // epilogue: d0,d1 -> row gid, cols 2*tid4..+1 ; d2,d3 -> row gid+8
    float* obase = sraw + ((size_t)b * LSEQ + qt * 128) * LSEQ + kt * 128;
    #pragma unroll
    for (int m = 0; m < 2; ++m) {
        const int r0 = mbase + m * 16 + gid;
        #pragma unroll
        for (int n = 0; n < 8; ++n) {
            const int c = nbase + n * 8 + 2 * tid4;
            float2 lo2 = make_float2(acc[m][n][0], acc[m][n][1]);
            float2 hi2 = make_float2(acc[m][n][2], acc[m][n][3]);
            *(float2*)(obase + (size_t)r0 * LSEQ + c)       = lo2;
            *(float2*)(obase + (size_t)(r0 + 8) * LSEQ + c) = hi2;
        }
    }
}

// ---------------------------------------------------------------------------
// Kernel 2: local_block[b,i,j] = sum_{a,c} W[a,c] * S_raw[b, 3i+a, 3j+c]
// ---------------------------------------------------------------------------
__global__ __launch_bounds__(256) void local_kernel(
    const float* __restrict__ sraw, const float* __restrict__ fc_w)
{
    __shared__ float rows[3][LSEQ];
    const int i = blockIdx.x;          // 0..255
    const int b = blockIdx.y;
    const int t = threadIdx.x;

    const float* base = sraw + ((size_t)b * LSEQ + 3 * i) * LSEQ;
    for (int idx = t; idx < 3 * LSEQ; idx += 256)
        rows[idx / LSEQ][idx % LSEQ] = base[(idx / LSEQ) * (size_t)LSEQ + idx % LSEQ];

    float w[9];
    #pragma unroll
    for (int x = 0; x < 9; ++x) w[x] = fc_w[x];
    __syncthreads();

    float s = 0.0f;
    #pragma unroll
    for (int a = 0; a < 3; ++a) {
        s += w[a * 3 + 0] * rows[a][3 * t + 0];
        s += w[a * 3 + 1] * rows[a][3 * t + 1];
        s += w[a * 3 + 2] * rows[a][3 * t + 2];
    }
    locbuf[((size_t)b * NBLK + i) * NBLK + t] = s;
}

// ---------------------------------------------------------------------------
// Kernel 3: attn = softmax_k( (S_raw + loc + 128*fc_b) * INV_T ), in place.
// ---------------------------------------------------------------------------
__global__ __launch_bounds__(256) void softmax_kernel(
    float* __restrict__ attn, const float* __restrict__ fc_b)
{
    const int row = blockIdx.x;                // 0..12287
    const int b = row / LSEQ, qrow = row % LSEQ;
    float* p = attn + (size_t)row * LSEQ;
    const float* loc = locbuf + ((size_t)b * NBLK + qrow / 3) * NBLK;
    const float bias = 128.0f * fc_b[0];
    const int t = threadIdx.x;

    __shared__ float red[8];

    float v0 = (p[t]       + loc[t / 3]         + bias) * INV_T;
    float v1 = (p[t + 256] + loc[(t + 256) / 3] + bias) * INV_T;
    float v2 = (p[t + 512] + loc[(t + 512) / 3] + bias) * INV_T;

    float m = fmaxf(fmaxf(v0, v1), v2);
    #pragma unroll
    for (int off = 16; off; off >>= 1)
        m = fmaxf(m, __shfl_xor_sync(0xffffffffu, m, off));
    if ((t & 31) == 0) red[t >> 5] = m;
    __syncthreads();
    m = fmaxf(fmaxf(fmaxf(red[0], red[1]), fmaxf(red[2], red[3])),
              fmaxf(fmaxf(red[4], red[5]), fmaxf(red[6], red[7])));
    __syncthreads();

    v0 = __expf(v0 - m); v1 = __expf(v1 - m); v2 = __expf(v2 - m);
    float s = v0 + v1 + v2;
    #pragma unroll
    for (int off = 16; off; off >>= 1)
        s += __shfl_xor_sync(0xffffffffu, s, off);
    if ((t & 31) == 0) red[t >> 5] = s;
    __syncthreads();
    s = (red[0] + red[1]) + (red[2] + red[3]) + (red[4] + red[5]) + (red[6] + red[7]);
    float inv = __frcp_rn(s);

    p[t]       = v0 * inv;
    p[t + 256] = v1 * inv;
    p[t + 512] = v2 * inv;
}

// ---------------------------------------------------------------------------
// Kernel 4: output = attn @ V (R7-measured SIMT version, plain FFMA).
// ---------------------------------------------------------------------------
__global__ __launch_bounds__(256) void out_kernel(
    const float* __restrict__ attn, const float* __restrict__ v,
    float* __restrict__ out)
{
    __shared__ float As[32][100];   // [kk][q-row]
    __shared__ float Vs[32][132];   // [kk][d-col]

    const int b  = blockIdx.y;
    const int qt = blockIdx.x;
    const int t  = threadIdx.x;
    const int ty = t >> 4;
    const int tx = t & 15;

    float acc[6][8] = {};

    const float* arow = attn + ((size_t)b * LSEQ + qt * 96) * LSEQ;
    const float* vb   = v + (size_t)b * LSEQ * DDIM;

    for (int k0 = 0; k0 < LSEQ; k0 += 32) {
        #pragma unroll
        for (int i = 0; i < 3; ++i) {
            int idx = t + i * 256;
            int row = idx >> 3;
            int c4  = idx & 7;
            float4 av = ld4(arow + (size_t)row * LSEQ + k0 + c4 * 4);
            As[c4 * 4 + 0][row] = av.x;
            As[c4 * 4 + 1][row] = av.y;
            As[c4 * 4 + 2][row] = av.z;
            As[c4 * 4 + 3][row] = av.w;
        }
        #pragma unroll
        for (int i = 0; i < 4; ++i) {
            int idx = t + i * 256;
            int row = idx >> 5;
            int c4  = idx & 31;
            *(float4*)&Vs[row][c4 * 4] = ld4(vb + (size_t)(k0 + row) * DDIM + c4 * 4);
        }
        __syncthreads();

        #pragma unroll
        for (int kk = 0; kk < 32; ++kk) {
            float2 a0 = *(const float2*)&As[kk][6 * ty + 0];
            float2 a1 = *(const float2*)&As[kk][6 * ty + 2];
            float2 a2 = *(const float2*)&As[kk][6 * ty + 4];
            float4 w0 = *(const float4*)&Vs[kk][tx * 8];
            float4 w1 = *(const float4*)&Vs[kk][tx * 8 + 4];
            const float av[6] = {a0.x, a0.y, a1.x, a1.y, a2.x, a2.y};
            const float wv[8] = {w0.x, w0.y, w0.z, w0.w, w1.x, w1.y, w1.z, w1.w};
            #pragma unroll
            for (int r = 0; r < 6; ++r)
                #pragma unroll
                for (int c = 0; c < 8; ++c)
                    acc[r][c] += av[r] * wv[c];
        }
        __syncthreads();
    }

    float* op = out + ((size_t)b * LSEQ + qt * 96 + 6 * ty) * DDIM + tx * 8;
    #pragma unroll
    for (int r = 0; r < 6; ++r) {
        float4 s0 = make_float4(acc[r][0], acc[r][1], acc[r][2], acc[r][3]);
        float4 s1 = make_float4(acc[r][4], acc[r][5], acc[r][6], acc[r][7]);
        *(float4*)(op + (size_t)r * DDIM)     = s0;
        *(float4*)(op + (size_t)r * DDIM + 4) = s1;
    }
}

// ---------------------------------------------------------------------------
extern "C" void kernel_launch(void* const* d_in, const int* in_sizes, int n_in,
                              void* d_out, int out_size)
{
    const float* q    = (const float*)d_in[0];
    const float* k    = (const float*)d_in[1];
    const float* v    = (const float*)d_in[2];
    const float* fc_w = (const float*)d_in[3];
    const float* fc_b = (const float*)d_in[4];

    float* out  = (float*)d_out;                                  // (B, L, D)
    float* attn = out + (size_t)BATCH * LSEQ * DDIM;              // (B, L, L)

    cudaFuncSetAttribute(scores_tc_kernel,
                         cudaFuncAttributeMaxDynamicSharedMemorySize, SMEM_DYN);

    dim3 g1(LSEQ / 128, LSEQ / 128, BATCH);
    scores_tc_kernel<<<g1, 256, SMEM_DYN>>>(q, k, attn);

    dim3 g2(NBLK, BATCH);
    local_kernel<<<g2, 256>>>(attn, fc_w);

    softmax_kernel<<<BATCH * LSEQ, 256>>>(attn, fc_b);

    dim3 g3(LSEQ / 96, BATCH);
    out_kernel<<<g3, 256>>>(attn, v, out);
}